// round 1
// baseline (speedup 1.0000x reference)
#include <cuda_runtime.h>
#include <math.h>

#define BB 4
#define SS 2048
#define EE 1024
#define HH 16
#define DD 64
#define MM (BB*SS)   // 8192

// Scratch (static device globals; allocation is forbidden)
__device__ float g_Q[BB*SS*EE];
__device__ float g_K[BB*SS*EE];
__device__ float g_V[BB*SS*EE];
__device__ float g_A[BB*SS*EE];

// ---------------------------------------------------------------------------
// C[M,N] = A[M,K] @ W[K,N] + bias[N]     (row-major, M%128==0, N%128==0, K%8==0)
// 128x128 tile, BK=8, 256 threads, 8x8 per-thread register tile
// ---------------------------------------------------------------------------
__global__ __launch_bounds__(256, 2)
void gemm_bias_kernel(const float* __restrict__ A, const float* __restrict__ W,
                      const float* __restrict__ bias, float* __restrict__ C,
                      int M, int N, int K)
{
    __shared__ float As[8][128];
    __shared__ float Bs[8][128];

    const int tid  = threadIdx.x;
    const int brow = blockIdx.y * 128;
    const int bcol = blockIdx.x * 128;

    const int arow = tid >> 1;          // 0..127
    const int acol = (tid & 1) * 4;     // 0 or 4
    const int bro  = tid >> 5;          // 0..7
    const int bco  = (tid & 31) * 4;    // 0..124

    const int ty = tid >> 4;            // 0..15 -> rows ty*8..+7
    const int tx = tid & 15;            // 0..15 -> cols tx*8..+7

    const float* Ap = A + (size_t)(brow + arow) * K + acol;
    const float* Wp = W + (size_t)bro * N + bcol + bco;

    float acc[8][8];
    #pragma unroll
    for (int i = 0; i < 8; i++)
        #pragma unroll
        for (int j = 0; j < 8; j++) acc[i][j] = 0.0f;

    for (int k0 = 0; k0 < K; k0 += 8) {
        float4 a4 = *(const float4*)(Ap + k0);
        float4 b4 = *(const float4*)(Wp + (size_t)k0 * N);
        As[acol + 0][arow] = a4.x;
        As[acol + 1][arow] = a4.y;
        As[acol + 2][arow] = a4.z;
        As[acol + 3][arow] = a4.w;
        *(float4*)&Bs[bro][bco] = b4;
        __syncthreads();

        #pragma unroll
        for (int k = 0; k < 8; k++) {
            float af[8], bf[8];
            #pragma unroll
            for (int i = 0; i < 8; i++) af[i] = As[k][ty * 8 + i];
            #pragma unroll
            for (int j = 0; j < 8; j++) bf[j] = Bs[k][tx * 8 + j];
            #pragma unroll
            for (int i = 0; i < 8; i++)
                #pragma unroll
                for (int j = 0; j < 8; j++)
                    acc[i][j] += af[i] * bf[j];
        }
        __syncthreads();
    }

    float bb[8];
    #pragma unroll
    for (int j = 0; j < 8; j++) bb[j] = bias[bcol + tx * 8 + j];

    #pragma unroll
    for (int i = 0; i < 8; i++) {
        float* Cp = C + (size_t)(brow + ty * 8 + i) * N + bcol + tx * 8;
        float4 r0, r1;
        r0.x = acc[i][0] + bb[0]; r0.y = acc[i][1] + bb[1];
        r0.z = acc[i][2] + bb[2]; r0.w = acc[i][3] + bb[3];
        r1.x = acc[i][4] + bb[4]; r1.y = acc[i][5] + bb[5];
        r1.z = acc[i][6] + bb[6]; r1.w = acc[i][7] + bb[7];
        *(float4*)(Cp + 0) = r0;
        *(float4*)(Cp + 4) = r1;
    }
}

// ---------------------------------------------------------------------------
// Flash attention (fp32): one CTA = 64 queries x one (b,h); loops KV tiles of 64.
// 256 threads (16x16), 4x4 scores / 4x4 output fragment per thread.
// smem tiles padded to 65 floats/row (<=2-way bank conflicts).
// ---------------------------------------------------------------------------
#define LDP 65
#define ATTN_SMEM (4 * 64 * LDP * (int)sizeof(float))   // 66560 B

__global__ __launch_bounds__(256)
void attn_kernel(const float* __restrict__ Q, const float* __restrict__ K,
                 const float* __restrict__ V, float* __restrict__ Out)
{
    extern __shared__ float sm[];
    float* Qs = sm;                 // [64][LDP]
    float* Ks = Qs + 64 * LDP;
    float* Vs = Ks + 64 * LDP;
    float* Ps = Vs + 64 * LDP;

    const int tid = threadIdx.x;
    const int tx  = tid & 15;
    const int ty  = tid >> 4;
    const int qt  = blockIdx.x;     // 0..31
    const int bh  = blockIdx.y;     // 0..63
    const int b   = bh >> 4;
    const int h   = bh & 15;

    const size_t base = (size_t)b * SS * EE + (size_t)h * DD;
    const float* Qg = Q + base + (size_t)qt * 64 * EE;
    const float* Kg = K + base;
    const float* Vg = V + base;

    // Load Q tile [64 x 64]
    for (int i = tid; i < 64 * 16; i += 256) {
        int r = i >> 4, c = (i & 15) * 4;
        float4 v = *(const float4*)(Qg + (size_t)r * EE + c);
        Qs[r * LDP + c + 0] = v.x;
        Qs[r * LDP + c + 1] = v.y;
        Qs[r * LDP + c + 2] = v.z;
        Qs[r * LDP + c + 3] = v.w;
    }

    float o[4][4];
    float m[4], l[4];
    #pragma unroll
    for (int i = 0; i < 4; i++) {
        m[i] = -1e30f; l[i] = 0.0f;
        #pragma unroll
        for (int j = 0; j < 4; j++) o[i][j] = 0.0f;
    }

    for (int kt = 0; kt < SS / 64; kt++) {
        __syncthreads();   // previous iteration done with Ks/Vs/Ps
        for (int i = tid; i < 64 * 16; i += 256) {
            int r = i >> 4, c = (i & 15) * 4;
            const size_t gro = (size_t)(kt * 64 + r) * EE + c;
            float4 kv = *(const float4*)(Kg + gro);
            float4 vv = *(const float4*)(Vg + gro);
            Ks[r * LDP + c + 0] = kv.x; Ks[r * LDP + c + 1] = kv.y;
            Ks[r * LDP + c + 2] = kv.z; Ks[r * LDP + c + 3] = kv.w;
            Vs[r * LDP + c + 0] = vv.x; Vs[r * LDP + c + 1] = vv.y;
            Vs[r * LDP + c + 2] = vv.z; Vs[r * LDP + c + 3] = vv.w;
        }
        __syncthreads();

        // Scores: s[i][j] = sum_d Qs[4ty+i][d] * Ks[4tx+j][d]
        float s[4][4];
        #pragma unroll
        for (int i = 0; i < 4; i++)
            #pragma unroll
            for (int j = 0; j < 4; j++) s[i][j] = 0.0f;

        #pragma unroll 8
        for (int d = 0; d < 64; d++) {
            float qf[4], kf[4];
            #pragma unroll
            for (int i = 0; i < 4; i++) qf[i] = Qs[(ty * 4 + i) * LDP + d];
            #pragma unroll
            for (int j = 0; j < 4; j++) kf[j] = Ks[(tx * 4 + j) * LDP + d];
            #pragma unroll
            for (int i = 0; i < 4; i++)
                #pragma unroll
                for (int j = 0; j < 4; j++)
                    s[i][j] += qf[i] * kf[j];
        }

        // Online softmax per row (rows owned by the 16 lanes sharing ty)
        #pragma unroll
        for (int i = 0; i < 4; i++) {
            float mx = -1e30f;
            #pragma unroll
            for (int j = 0; j < 4; j++) {
                s[i][j] *= 0.125f;                  // 1/sqrt(64)
                mx = fmaxf(mx, s[i][j]);
            }
            #pragma unroll
            for (int off = 8; off >= 1; off >>= 1)
                mx = fmaxf(mx, __shfl_xor_sync(0xffffffffu, mx, off, 16));
            float nm = fmaxf(m[i], mx);
            float corr = __expf(m[i] - nm);
            float rs = 0.0f;
            #pragma unroll
            for (int j = 0; j < 4; j++) {
                s[i][j] = __expf(s[i][j] - nm);
                rs += s[i][j];
            }
            #pragma unroll
            for (int off = 8; off >= 1; off >>= 1)
                rs += __shfl_xor_sync(0xffffffffu, rs, off, 16);
            l[i] = l[i] * corr + rs;
            m[i] = nm;
            #pragma unroll
            for (int j = 0; j < 4; j++) o[i][j] *= corr;
            #pragma unroll
            for (int j = 0; j < 4; j++)
                Ps[(ty * 4 + i) * LDP + tx * 4 + j] = s[i][j];
        }
        __syncthreads();

        // O += P @ V  (o cols = head dims 4tx..+3)
        #pragma unroll 8
        for (int kk = 0; kk < 64; kk++) {
            float pf[4], vf[4];
            #pragma unroll
            for (int i = 0; i < 4; i++) pf[i] = Ps[(ty * 4 + i) * LDP + kk];
            #pragma unroll
            for (int j = 0; j < 4; j++) vf[j] = Vs[kk * LDP + tx * 4 + j];
            #pragma unroll
            for (int i = 0; i < 4; i++)
                #pragma unroll
                for (int j = 0; j < 4; j++)
                    o[i][j] += pf[i] * vf[j];
        }
    }

    // Epilogue: normalize and store into [B,S,E] (head-major columns == concat)
    #pragma unroll
    for (int i = 0; i < 4; i++) {
        float inv = 1.0f / l[i];
        float* Op = Out + ((size_t)b * SS + (size_t)qt * 64 + ty * 4 + i) * EE
                        + h * DD + tx * 4;
        #pragma unroll
        for (int j = 0; j < 4; j++) Op[j] = o[i][j] * inv;
    }
}

// ---------------------------------------------------------------------------
extern "C" void kernel_launch(void* const* d_in, const int* in_sizes, int n_in,
                              void* d_out, int out_size)
{
    const float* x  = (const float*)d_in[0];
    const float* Wq = (const float*)d_in[1];
    const float* bq = (const float*)d_in[2];
    const float* Wk = (const float*)d_in[3];
    const float* bk = (const float*)d_in[4];
    const float* Wv = (const float*)d_in[5];
    const float* bv = (const float*)d_in[6];
    const float* Wo = (const float*)d_in[7];
    const float* bo = (const float*)d_in[8];
    float* out = (float*)d_out;

    float *Q, *K, *V, *A;
    cudaGetSymbolAddress((void**)&Q, g_Q);
    cudaGetSymbolAddress((void**)&K, g_K);
    cudaGetSymbolAddress((void**)&V, g_V);
    cudaGetSymbolAddress((void**)&A, g_A);

    cudaFuncSetAttribute(attn_kernel,
                         cudaFuncAttributeMaxDynamicSharedMemorySize, ATTN_SMEM);

    dim3 gblk(256);
    dim3 ggrd(EE / 128, MM / 128);   // (8, 64)

    gemm_bias_kernel<<<ggrd, gblk>>>(x, Wq, bq, Q, MM, EE, EE);
    gemm_bias_kernel<<<ggrd, gblk>>>(x, Wk, bk, K, MM, EE, EE);
    gemm_bias_kernel<<<ggrd, gblk>>>(x, Wv, bv, V, MM, EE, EE);

    dim3 agrd(SS / 64, BB * HH);     // (32, 64)
    attn_kernel<<<agrd, 256, ATTN_SMEM>>>(Q, K, V, A);

    gemm_bias_kernel<<<ggrd, gblk>>>(A, Wo, bo, out, MM, EE, EE);
}